// round 9
// baseline (speedup 1.0000x reference)
#include <cuda_runtime.h>
#include <cuda_bf16.h>
#include <math.h>

#define T_STEPS 200
#define BATCH   128
#define DIN     784
#define HID     500
#define NOUT    10
#define MROWS   (BATCH * T_STEPS)   // 25600
#define DECAY_M 0.77880078307140487f
#define EPS_BN  1e-5f
#define NSTATB  800

// ------------------------- device scratch (no allocs allowed) ---------------
__device__ float g_buf0[MROWS * DIN];
__device__ float g_buf1[MROWS * HID];
__device__ float g_buf2[MROWS * HID];
__device__ float g_buf3[MROWS * NOUT];
__device__ double g_psumd[NSTATB * DIN];
__device__ double g_psqd [NSTATB * DIN];
__device__ float g_mean[DIN];
__device__ float g_rs[DIN];

__device__ __forceinline__ float* bufsel(int s) {
    return s == 0 ? g_buf0 : (s == 1 ? g_buf1 : g_buf2);
}

// 4-op compensated accumulate: (s,c) += a*b   (proven: rel_err == 0.0)
__device__ __forceinline__ void kacc2(float a, float b, float& s, float& c) {
    float y = __fmaf_rn(a, b, -c);
    float t = __fadd_rn(s, y);
    c = __fsub_rn(__fsub_rn(t, s), y);
    s = t;
}

__device__ __forceinline__ float sigmoid_exact(float x) {
    return __fdiv_rn(1.0f, __fadd_rn(1.0f, expf(-x)));
}

// ======================= GEMM core ==========================================
// Block 128x64, 256 threads, 8x4 per thread, BK=16, double-buffered smem.
// MODE 0: A gathered from inputs[b,i,t] (K=DIN);  MODE 1: A row-major [M,K].
template <int MODE>
__device__ __forceinline__ void gemm_body(
    const float* __restrict__ Asrc, const float* __restrict__ B,
    const float* __restrict__ bias, float* __restrict__ Cdst, int N, int K) {
    __shared__ __align__(16) float As[2][16][132];
    __shared__ __align__(16) float Bs[2][16][68];
    const int m0 = blockIdx.x * 128, n0 = blockIdx.y * 64;
    const int tid = threadIdx.x;
    const int tx = tid & 15, ty = tid >> 4;   // tx: n (4 cols), ty: m (8 rows)
    const int nchunks = (K + 15) / 16;

    float s[8][4], c[8][4];
#pragma unroll
    for (int i = 0; i < 8; i++)
#pragma unroll
        for (int j = 0; j < 4; j++) { s[i][j] = 0.f; c[i][j] = 0.f; }

    // load indices: A element per l: e = tid + l*256; m = e>>4... we need
    // 128 rows x 16 k = 2048 elems / 256 thr = 8 each.
    // Use k-fast layout for coalescing: m = e >> 4, k = e & 15.
    // B: 64 rows x 16 k = 1024 / 256 = 4 each: n = e >> 4, k = e & 15.
    float pa[8], pb[4];

    // ---- load chunk 0 directly to smem[0]
    {
        const int k0 = 0;
#pragma unroll
        for (int l = 0; l < 8; l++) {
            int e = tid + l * 256;
            int m = e >> 4, k = e & 15;
            float v;
            if (MODE == 0) {
                int r = m0 + m;
                int bb = r / T_STEPS;
                int t  = r - bb * T_STEPS;
                v = Asrc[bb * (DIN * T_STEPS) + (k0 + k) * T_STEPS + t];
            } else {
                v = (k0 + k < K) ? Asrc[(m0 + m) * K + (k0 + k)] : 0.f;
            }
            As[0][k][m] = v;
        }
#pragma unroll
        for (int l = 0; l < 4; l++) {
            int e = tid + l * 256;
            int n = e >> 4, k = e & 15;
            float v = 0.f;
            if ((n0 + n < N) && (k0 + k < K)) v = B[(n0 + n) * K + (k0 + k)];
            Bs[0][k][n] = v;
        }
    }
    __syncthreads();

    int cur = 0;
    for (int ch = 0; ch < nchunks; ch++) {
        // prefetch next chunk into registers
        if (ch + 1 < nchunks) {
            const int k0 = (ch + 1) * 16;
#pragma unroll
            for (int l = 0; l < 8; l++) {
                int e = tid + l * 256;
                int m = e >> 4, k = e & 15;
                float v;
                if (MODE == 0) {
                    int r = m0 + m;
                    int bb = r / T_STEPS;
                    int t  = r - bb * T_STEPS;
                    v = Asrc[bb * (DIN * T_STEPS) + (k0 + k) * T_STEPS + t];
                } else {
                    v = (k0 + k < K) ? Asrc[(m0 + m) * K + (k0 + k)] : 0.f;
                }
                pa[l] = v;
            }
#pragma unroll
            for (int l = 0; l < 4; l++) {
                int e = tid + l * 256;
                int n = e >> 4, k = e & 15;
                float v = 0.f;
                if ((n0 + n < N) && (k0 + k < K)) v = B[(n0 + n) * K + (k0 + k)];
                pb[l] = v;
            }
        }

        // compute on current buffer
#pragma unroll
        for (int k = 0; k < 16; k++) {
            float a0[8], b0[4];
            const float4* pa4 = reinterpret_cast<const float4*>(&As[cur][k][ty * 8]);
            float4 av0 = pa4[0], av1 = pa4[1];
            float4 bv = *reinterpret_cast<const float4*>(&Bs[cur][k][tx * 4]);
            a0[0] = av0.x; a0[1] = av0.y; a0[2] = av0.z; a0[3] = av0.w;
            a0[4] = av1.x; a0[5] = av1.y; a0[6] = av1.z; a0[7] = av1.w;
            b0[0] = bv.x; b0[1] = bv.y; b0[2] = bv.z; b0[3] = bv.w;
#pragma unroll
            for (int i = 0; i < 8; i++)
#pragma unroll
                for (int j = 0; j < 4; j++) kacc2(a0[i], b0[j], s[i][j], c[i][j]);
        }

        // store prefetched regs into the other buffer, then barrier + swap
        if (ch + 1 < nchunks) {
            int nxt = cur ^ 1;
#pragma unroll
            for (int l = 0; l < 8; l++) {
                int e = tid + l * 256;
                int m = e >> 4, k = e & 15;
                As[nxt][k][m] = pa[l];
            }
#pragma unroll
            for (int l = 0; l < 4; l++) {
                int e = tid + l * 256;
                int n = e >> 4, k = e & 15;
                Bs[nxt][k][n] = pb[l];
            }
            __syncthreads();
            cur = nxt;
        }
    }

#pragma unroll
    for (int i = 0; i < 8; i++) {
        int m = m0 + ty * 8 + i;
#pragma unroll
        for (int j = 0; j < 4; j++) {
            int n = n0 + tx * 4 + j;
            if (n < N) {
                float acc = __fsub_rn(s[i][j], c[i][j]);
                Cdst[m * N + n] = __fadd_rn(acc, bias[n]);
            }
        }
    }
}

__global__ void __launch_bounds__(256) gemm_mlp_comp_kernel(
    const float* __restrict__ In, const float* __restrict__ W,
    const float* __restrict__ bias) {
    gemm_body<0>(In, W, bias, g_buf0, DIN, DIN);
}

__global__ void __launch_bounds__(256) gemm_nt_comp_kernel(
    int asel, int csel, const float* __restrict__ B,
    const float* __restrict__ bias, int N, int K) {
    gemm_body<1>(bufsel(asel), B, bias, bufsel(csel), N, K);
}

// ------------------------- BN stats: single pass fp64 sum + sumsq -----------
__global__ void bn_stats_kernel() {
    int blk = blockIdx.x;
    int tid = threadIdx.x;
    double ls[4] = {0.0, 0.0, 0.0, 0.0};
    double lq[4] = {0.0, 0.0, 0.0, 0.0};
    int r0 = blk * (MROWS / NSTATB);
    for (int r = r0; r < r0 + (MROWS / NSTATB); r++) {
        const float* row = g_buf0 + r * DIN;
#pragma unroll
        for (int j = 0; j < 4; j++) {
            int c = tid + j * 256;
            if (c < DIN) {
                double v = (double)row[c];
                ls[j] += v;
                lq[j] += v * v;
            }
        }
    }
#pragma unroll
    for (int j = 0; j < 4; j++) {
        int c = tid + j * 256;
        if (c < DIN) {
            g_psumd[blk * DIN + c] = ls[j];
            g_psqd [blk * DIN + c] = lq[j];
        }
    }
}

__global__ void bn_fin_kernel() {
    int c = blockIdx.x * blockDim.x + threadIdx.x;
    if (c >= DIN) return;
    double s = 0.0, q = 0.0;
    for (int i = 0; i < NSTATB; i++) {
        s += g_psumd[i * DIN + c];
        q += g_psqd [i * DIN + c];
    }
    float sumf = (float)s;
    g_mean[c] = __fdiv_rn(sumf, (float)MROWS);
    double meand = s / (double)MROWS;
    double vard = q / (double)MROWS - meand * meand;
    float var = (float)vard;
    g_rs[c] = rsqrtf(__fadd_rn(var, EPS_BN));
}

// ------------------------- fused BN apply + sigmoid + axon1 (in place) ------
__global__ void axon1_bn_kernel(const float* __restrict__ gamma,
                                const float* __restrict__ beta,
                                const float* __restrict__ a1,
                                const float* __restrict__ a2) {
    int idx = blockIdx.x * blockDim.x + threadIdx.x;
    if (idx >= BATCH * DIN) return;
    int b = idx / DIN, c = idx - b * DIN;
    float A1 = a1[c], A2 = a2[c];
    float mean = g_mean[c], rs = g_rs[c], gm = gamma[c], bt = beta[c];
    float p1 = 0.f, p2 = 0.f;
    int off = b * T_STEPS * DIN + c;
    for (int t = 0; t < T_STEPS; t++, off += DIN) {
        float v = __fsub_rn(g_buf0[off], mean);
        v = __fmul_rn(gm, v);
        v = __fmul_rn(v, rs);
        v = __fadd_rn(v, bt);
        float x = sigmoid_exact(v);
        float p = __fadd_rn(__fadd_rn(__fmul_rn(A1, p1), __fmul_rn(A2, p2)), x);
        g_buf0[off] = p;
        p2 = p1;
        p1 = p;
    }
}

// -------- fused LIF (layer l) + dropout mask + axon (layer l+1), in place ---
// Per element, identical op order to the separate lif/axon kernels.
__global__ void lif_axon_kernel(int bsel, const float* __restrict__ mask,
                                const float* __restrict__ a1,
                                const float* __restrict__ a2) {
    float* buf = bufsel(bsel);
    int idx = blockIdx.x * blockDim.x + threadIdx.x;
    if (idx >= BATCH * HID) return;
    int b = idx / HID, cch = idx - b * HID;
    float A1 = a1[cch], A2 = a2[cch];
    float v = 0.f, sp = 0.f;
    float p1 = 0.f, p2 = 0.f;
    int off = b * T_STEPS * HID + cch;
    int moff = (b * HID + cch) * T_STEPS;
    for (int t = 0; t < T_STEPS; t++, off += HID) {
        float z = buf[off];
        v = __fadd_rn(__fmul_rn(__fmul_rn(DECAY_M, v), __fsub_rn(1.0f, sp)), z);
        sp = (v > 1.0f) ? 1.0f : 0.0f;
        float x = __fmul_rn(sp, mask[moff + t]);
        float p = __fadd_rn(__fadd_rn(__fmul_rn(A1, p1), __fmul_rn(A2, p2)), x);
        buf[off] = p;
        p2 = p1;
        p1 = p;
    }
}

// ------------------------- GEMM3 (N=10): compensated ------------------------
__global__ void __launch_bounds__(256) gemm3_kernel(
    const float* __restrict__ W3, const float* __restrict__ b3) {
    __shared__ float sW[NOUT][HID];
    int tid = threadIdx.x;
    for (int i = tid; i < NOUT * HID; i += 256) sW[i / HID][i % HID] = W3[i];
    __syncthreads();
    int idx = blockIdx.x * 256 + tid;
    int r = idx / NOUT, o = idx - r * NOUT;
    const float* a = g_buf2 + r * HID;
    float s = 0.f, c = 0.f;
    for (int k = 0; k < HID; k++) kacc2(a[k], sW[o][k], s, c);
    float acc = __fsub_rn(s, c);
    g_buf3[r * NOUT + o] = __fadd_rn(acc, b3[o]);
}

// ------------------------- final LIF + output transpose [B,10,T] ------------
__global__ void lif3_out_kernel(float* __restrict__ out) {
    int idx = blockIdx.x * blockDim.x + threadIdx.x;
    if (idx >= BATCH * NOUT) return;
    int b = idx / NOUT, o = idx - b * NOUT;
    float v = 0.f, s = 0.f;
    for (int t = 0; t < T_STEPS; t++) {
        float z = g_buf3[(b * T_STEPS + t) * NOUT + o];
        v = __fadd_rn(__fmul_rn(__fmul_rn(DECAY_M, v), __fsub_rn(1.0f, s)), z);
        s = (v > 1.0f) ? 1.0f : 0.0f;
        out[(b * NOUT + o) * T_STEPS + t] = s;
    }
}

// ------------------------- launch -------------------------------------------
extern "C" void kernel_launch(void* const* d_in, const int* in_sizes, int n_in,
                              void* d_out, int out_size) {
    const float* inputs = (const float*)d_in[0];
    const float* W_mlp  = (const float*)d_in[1];
    const float* b_mlp  = (const float*)d_in[2];
    const float* gamma  = (const float*)d_in[3];
    const float* beta   = (const float*)d_in[4];
    const float* a1_1   = (const float*)d_in[5];
    const float* a2_1   = (const float*)d_in[6];
    const float* W1     = (const float*)d_in[7];
    const float* b1     = (const float*)d_in[8];
    const float* a1_2   = (const float*)d_in[9];
    const float* a2_2   = (const float*)d_in[10];
    const float* W2     = (const float*)d_in[11];
    const float* b2     = (const float*)d_in[12];
    const float* a1_3   = (const float*)d_in[13];
    const float* a2_3   = (const float*)d_in[14];
    const float* W3     = (const float*)d_in[15];
    const float* b3     = (const float*)d_in[16];
    const float* mask1  = (const float*)d_in[17];
    const float* mask2  = (const float*)d_in[18];
    float* out = (float*)d_out;

    gemm_mlp_comp_kernel<<<dim3(MROWS / 128, (DIN + 63) / 64), 256>>>(inputs, W_mlp, b_mlp);

    bn_stats_kernel<<<NSTATB, 256>>>();
    bn_fin_kernel<<<(DIN + 255) / 256, 256>>>();

    axon1_bn_kernel<<<(BATCH * DIN + 255) / 256, 256>>>(gamma, beta, a1_1, a2_1);
    gemm_nt_comp_kernel<<<dim3(MROWS / 128, (HID + 63) / 64), 256>>>(0, 1, W1, b1, HID, DIN);
    lif_axon_kernel<<<(BATCH * HID + 255) / 256, 256>>>(1, mask1, a1_2, a2_2);

    gemm_nt_comp_kernel<<<dim3(MROWS / 128, (HID + 63) / 64), 256>>>(1, 2, W2, b2, HID, HID);
    lif_axon_kernel<<<(BATCH * HID + 255) / 256, 256>>>(2, mask2, a1_3, a2_3);

    gemm3_kernel<<<MROWS * NOUT / 256, 256>>>(W3, b3);
    lif3_out_kernel<<<(BATCH * NOUT + 255) / 256, 256>>>(out);
}

// round 10
// speedup vs baseline: 1.6921x; 1.6921x over previous
#include <cuda_runtime.h>
#include <cuda_bf16.h>
#include <math.h>

#define T_STEPS 200
#define BATCH   128
#define DIN     784
#define HID     500
#define NOUT    10
#define MROWS   (BATCH * T_STEPS)   // 25600
#define DECAY_M 0.77880078307140487f
#define EPS_BN  1e-5f
#define NSTATB  800

// ------------------------- device scratch (no allocs allowed) ---------------
__device__ float g_buf0[MROWS * DIN];
__device__ float g_buf1[MROWS * HID];
__device__ float g_buf2[MROWS * HID];
__device__ float g_buf3[MROWS * NOUT];
__device__ double g_psumd[NSTATB * DIN];
__device__ double g_psqd [NSTATB * DIN];
__device__ float g_mean[DIN];
__device__ float g_rs[DIN];

__device__ __forceinline__ float* bufsel(int s) {
    return s == 0 ? g_buf0 : (s == 1 ? g_buf1 : g_buf2);
}

// Kahan two-sum merge of a value r into (s,c):
__device__ __forceinline__ void kmerge(float r, float& s, float& c) {
    float y = __fsub_rn(r, c);
    float t = __fadd_rn(s, y);
    c = __fsub_rn(__fsub_rn(t, s), y);
    s = t;
}

// 4-op compensated accumulate (gemm3)
__device__ __forceinline__ void kacc2(float a, float b, float& s, float& c) {
    float y = __fmaf_rn(a, b, -c);
    float t = __fadd_rn(s, y);
    c = __fsub_rn(__fsub_rn(t, s), y);
    s = t;
}

__device__ __forceinline__ float sigmoid_exact(float x) {
    return __fdiv_rn(1.0f, __fadd_rn(1.0f, expf(-x)));
}

// ======================= GEMM core ==========================================
// Block 64x64, 256 threads, 4x4/thread, BK=16 segments.
// Per 16-k segment: plain FMA chain into r, then Kahan-merge into (s,c).
// MODE 0: A gathered from inputs[b,i,t] (K=DIN);  MODE 1: A row-major [M,K].
template <int MODE>
__device__ __forceinline__ void gemm_body(
    const float* __restrict__ Asrc, const float* __restrict__ B,
    const float* __restrict__ bias, float* __restrict__ Cdst, int N, int K) {
    __shared__ __align__(16) float As[16][68];
    __shared__ __align__(16) float Bs[16][68];
    const int m0 = blockIdx.x * 64, n0 = blockIdx.y * 64;
    const int tid = threadIdx.x;
    const int tx = tid & 15, ty = tid >> 4;
    const int nchunks = (K + 15) / 16;

    float s[4][4], c[4][4];
#pragma unroll
    for (int i = 0; i < 4; i++)
#pragma unroll
        for (int j = 0; j < 4; j++) { s[i][j] = 0.f; c[i][j] = 0.f; }

    for (int ch = 0; ch < nchunks; ch++) {
        const int k0 = ch * 16;
        // ---- load A tile: 64 m x 16 k = 1024 elems, 4/thread
        if (MODE == 0) {
            // inputs: consecutive t (=m) contiguous -> m-fast
#pragma unroll
            for (int l = 0; l < 4; l++) {
                int e = tid + l * 256;
                int m = e & 63, k = e >> 6;
                int r = m0 + m;
                int bb = r / T_STEPS;
                int t  = r - bb * T_STEPS;
                As[k][m] = Asrc[bb * (DIN * T_STEPS) + (k0 + k) * T_STEPS + t];
            }
        } else {
            // row-major [M,K]: consecutive k contiguous -> k-fast
#pragma unroll
            for (int l = 0; l < 4; l++) {
                int e = tid + l * 256;
                int m = e >> 4, k = e & 15;
                As[k][m] = (k0 + k < K) ? Asrc[(m0 + m) * K + (k0 + k)] : 0.f;
            }
        }
        // ---- load B tile: 64 n x 16 k, k-fast
#pragma unroll
        for (int l = 0; l < 4; l++) {
            int e = tid + l * 256;
            int n = e >> 4, k = e & 15;
            float v = 0.f;
            if ((n0 + n < N) && (k0 + k < K)) v = B[(n0 + n) * K + (k0 + k)];
            Bs[k][n] = v;
        }
        __syncthreads();

        // ---- segment chains (16 plain FMAs per accumulator)
        float r[4][4];
#pragma unroll
        for (int k = 0; k < 16; k++) {
            float4 av = *reinterpret_cast<const float4*>(&As[k][ty * 4]);
            float4 bv = *reinterpret_cast<const float4*>(&Bs[k][tx * 4]);
            float a[4] = {av.x, av.y, av.z, av.w};
            float b[4] = {bv.x, bv.y, bv.z, bv.w};
            if (k == 0) {
#pragma unroll
                for (int i = 0; i < 4; i++)
#pragma unroll
                    for (int j = 0; j < 4; j++)
                        r[i][j] = __fmul_rn(a[i], b[j]);
            } else {
#pragma unroll
                for (int i = 0; i < 4; i++)
#pragma unroll
                    for (int j = 0; j < 4; j++)
                        r[i][j] = __fmaf_rn(a[i], b[j], r[i][j]);
            }
        }
        // ---- compensated merge of segment sums
#pragma unroll
        for (int i = 0; i < 4; i++)
#pragma unroll
            for (int j = 0; j < 4; j++) kmerge(r[i][j], s[i][j], c[i][j]);
        __syncthreads();
    }

#pragma unroll
    for (int i = 0; i < 4; i++) {
        int m = m0 + ty * 4 + i;
#pragma unroll
        for (int j = 0; j < 4; j++) {
            int n = n0 + tx * 4 + j;
            if (n < N) {
                float acc = __fsub_rn(s[i][j], c[i][j]);
                Cdst[m * N + n] = __fadd_rn(acc, bias[n]);
            }
        }
    }
}

__global__ void __launch_bounds__(256) gemm_mlp_comp_kernel(
    const float* __restrict__ In, const float* __restrict__ W,
    const float* __restrict__ bias) {
    gemm_body<0>(In, W, bias, g_buf0, DIN, DIN);
}

__global__ void __launch_bounds__(256) gemm_nt_comp_kernel(
    int asel, int csel, const float* __restrict__ B,
    const float* __restrict__ bias, int N, int K) {
    gemm_body<1>(bufsel(asel), B, bias, bufsel(csel), N, K);
}

// ------------------------- BN stats: single pass fp64 sum + sumsq -----------
__global__ void bn_stats_kernel() {
    int blk = blockIdx.x;
    int tid = threadIdx.x;
    double ls[4] = {0.0, 0.0, 0.0, 0.0};
    double lq[4] = {0.0, 0.0, 0.0, 0.0};
    int r0 = blk * (MROWS / NSTATB);
    for (int r = r0; r < r0 + (MROWS / NSTATB); r++) {
        const float* row = g_buf0 + r * DIN;
#pragma unroll
        for (int j = 0; j < 4; j++) {
            int c = tid + j * 256;
            if (c < DIN) {
                double v = (double)row[c];
                ls[j] += v;
                lq[j] += v * v;
            }
        }
    }
#pragma unroll
    for (int j = 0; j < 4; j++) {
        int c = tid + j * 256;
        if (c < DIN) {
            g_psumd[blk * DIN + c] = ls[j];
            g_psqd [blk * DIN + c] = lq[j];
        }
    }
}

__global__ void bn_fin_kernel() {
    int c = blockIdx.x * blockDim.x + threadIdx.x;
    if (c >= DIN) return;
    double s = 0.0, q = 0.0;
    for (int i = 0; i < NSTATB; i++) {
        s += g_psumd[i * DIN + c];
        q += g_psqd [i * DIN + c];
    }
    float sumf = (float)s;
    g_mean[c] = __fdiv_rn(sumf, (float)MROWS);
    double meand = s / (double)MROWS;
    double vard = q / (double)MROWS - meand * meand;
    float var = (float)vard;
    g_rs[c] = rsqrtf(__fadd_rn(var, EPS_BN));
}

// ------------------------- fused BN apply + sigmoid + axon1 (in place) ------
__global__ void axon1_bn_kernel(const float* __restrict__ gamma,
                                const float* __restrict__ beta,
                                const float* __restrict__ a1,
                                const float* __restrict__ a2) {
    int idx = blockIdx.x * blockDim.x + threadIdx.x;
    if (idx >= BATCH * DIN) return;
    int b = idx / DIN, c = idx - b * DIN;
    float A1 = a1[c], A2 = a2[c];
    float mean = g_mean[c], rs = g_rs[c], gm = gamma[c], bt = beta[c];
    float p1 = 0.f, p2 = 0.f;
    int off = b * T_STEPS * DIN + c;
    for (int t = 0; t < T_STEPS; t++, off += DIN) {
        float v = __fsub_rn(g_buf0[off], mean);
        v = __fmul_rn(gm, v);
        v = __fmul_rn(v, rs);
        v = __fadd_rn(v, bt);
        float x = sigmoid_exact(v);
        float p = __fadd_rn(__fadd_rn(__fmul_rn(A1, p1), __fmul_rn(A2, p2)), x);
        g_buf0[off] = p;
        p2 = p1;
        p1 = p;
    }
}

// -------- fused LIF (layer l) + dropout mask + axon (layer l+1), in place ---
__global__ void lif_axon_kernel(int bsel, const float* __restrict__ mask,
                                const float* __restrict__ a1,
                                const float* __restrict__ a2) {
    float* buf = bufsel(bsel);
    int idx = blockIdx.x * blockDim.x + threadIdx.x;
    if (idx >= BATCH * HID) return;
    int b = idx / HID, cch = idx - b * HID;
    float A1 = a1[cch], A2 = a2[cch];
    float v = 0.f, sp = 0.f;
    float p1 = 0.f, p2 = 0.f;
    int off = b * T_STEPS * HID + cch;
    int moff = (b * HID + cch) * T_STEPS;
    for (int t = 0; t < T_STEPS; t++, off += HID) {
        float z = buf[off];
        v = __fadd_rn(__fmul_rn(__fmul_rn(DECAY_M, v), __fsub_rn(1.0f, sp)), z);
        sp = (v > 1.0f) ? 1.0f : 0.0f;
        float x = __fmul_rn(sp, mask[moff + t]);
        float p = __fadd_rn(__fadd_rn(__fmul_rn(A1, p1), __fmul_rn(A2, p2)), x);
        buf[off] = p;
        p2 = p1;
        p1 = p;
    }
}

// ------------------------- GEMM3 (N=10): compensated ------------------------
__global__ void __launch_bounds__(256) gemm3_kernel(
    const float* __restrict__ W3, const float* __restrict__ b3) {
    __shared__ float sW[NOUT][HID];
    int tid = threadIdx.x;
    for (int i = tid; i < NOUT * HID; i += 256) sW[i / HID][i % HID] = W3[i];
    __syncthreads();
    int idx = blockIdx.x * 256 + tid;
    int r = idx / NOUT, o = idx - r * NOUT;
    const float* a = g_buf2 + r * HID;
    float s = 0.f, c = 0.f;
    for (int k = 0; k < HID; k++) kacc2(a[k], sW[o][k], s, c);
    float acc = __fsub_rn(s, c);
    g_buf3[r * NOUT + o] = __fadd_rn(acc, b3[o]);
}

// ------------------------- final LIF + output transpose [B,10,T] ------------
__global__ void lif3_out_kernel(float* __restrict__ out) {
    int idx = blockIdx.x * blockDim.x + threadIdx.x;
    if (idx >= BATCH * NOUT) return;
    int b = idx / NOUT, o = idx - b * NOUT;
    float v = 0.f, s = 0.f;
    for (int t = 0; t < T_STEPS; t++) {
        float z = g_buf3[(b * T_STEPS + t) * NOUT + o];
        v = __fadd_rn(__fmul_rn(__fmul_rn(DECAY_M, v), __fsub_rn(1.0f, s)), z);
        s = (v > 1.0f) ? 1.0f : 0.0f;
        out[(b * NOUT + o) * T_STEPS + t] = s;
    }
}

// ------------------------- launch -------------------------------------------
extern "C" void kernel_launch(void* const* d_in, const int* in_sizes, int n_in,
                              void* d_out, int out_size) {
    const float* inputs = (const float*)d_in[0];
    const float* W_mlp  = (const float*)d_in[1];
    const float* b_mlp  = (const float*)d_in[2];
    const float* gamma  = (const float*)d_in[3];
    const float* beta   = (const float*)d_in[4];
    const float* a1_1   = (const float*)d_in[5];
    const float* a2_1   = (const float*)d_in[6];
    const float* W1     = (const float*)d_in[7];
    const float* b1     = (const float*)d_in[8];
    const float* a1_2   = (const float*)d_in[9];
    const float* a2_2   = (const float*)d_in[10];
    const float* W2     = (const float*)d_in[11];
    const float* b2     = (const float*)d_in[12];
    const float* a1_3   = (const float*)d_in[13];
    const float* a2_3   = (const float*)d_in[14];
    const float* W3     = (const float*)d_in[15];
    const float* b3     = (const float*)d_in[16];
    const float* mask1  = (const float*)d_in[17];
    const float* mask2  = (const float*)d_in[18];
    float* out = (float*)d_out;

    gemm_mlp_comp_kernel<<<dim3(MROWS / 64, (DIN + 63) / 64), 256>>>(inputs, W_mlp, b_mlp);

    bn_stats_kernel<<<NSTATB, 256>>>();
    bn_fin_kernel<<<(DIN + 255) / 256, 256>>>();

    axon1_bn_kernel<<<(BATCH * DIN + 255) / 256, 256>>>(gamma, beta, a1_1, a2_1);
    gemm_nt_comp_kernel<<<dim3(MROWS / 64, (HID + 63) / 64), 256>>>(0, 1, W1, b1, HID, DIN);
    lif_axon_kernel<<<(BATCH * HID + 255) / 256, 256>>>(1, mask1, a1_2, a2_2);

    gemm_nt_comp_kernel<<<dim3(MROWS / 64, (HID + 63) / 64), 256>>>(1, 2, W2, b2, HID, HID);
    lif_axon_kernel<<<(BATCH * HID + 255) / 256, 256>>>(2, mask2, a1_3, a2_3);

    gemm3_kernel<<<MROWS * NOUT / 256, 256>>>(W3, b3);
    lif3_out_kernel<<<(BATCH * NOUT + 255) / 256, 256>>>(out);
}

// round 13
// speedup vs baseline: 1.9834x; 1.1721x over previous
#include <cuda_runtime.h>
#include <cuda_bf16.h>
#include <math.h>
#include <stdint.h>

#define T_STEPS 200
#define BATCH   128
#define DIN     784
#define HID     500
#define NOUT    10
#define MROWS   (BATCH * T_STEPS)   // 25600
#define DECAY_M 0.77880078307140487f
#define EPS_BN  1e-5f
#define NSTATB  800
#define KP1     832
#define KP2     512

#define ROWB    144
#define ASPL    (128 * ROWB)
#define BSPL    (64 * ROWB)
#define SMEM_B0 (3 * ASPL)
#define SMEM_TOT (SMEM_B0 + 3 * BSPL)   // 82944

// ------------------------- device scratch (no allocs allowed) ---------------
__device__ float g_buf0[MROWS * DIN];
__device__ float g_buf1[MROWS * HID];
__device__ float g_buf2[MROWS * HID];
__device__ float g_buf3[MROWS * NOUT];
__device__ double g_psumd[NSTATB * DIN];
__device__ double g_psqd [NSTATB * DIN];
__device__ float g_mean[DIN];
__device__ float g_rs[DIN];
__device__ __nv_bfloat16 g_Ah[MROWS * KP1];
__device__ __nv_bfloat16 g_Am[MROWS * KP1];
__device__ __nv_bfloat16 g_Al[MROWS * KP1];
__device__ __nv_bfloat16 g_Wh[800 * KP1];
__device__ __nv_bfloat16 g_Wm[800 * KP1];
__device__ __nv_bfloat16 g_Wl[800 * KP1];

__device__ __forceinline__ float* bufsel(int s) {
    return s == 0 ? g_buf0 : (s == 1 ? g_buf1 : g_buf2);
}

// Kahan two-sum merge of value r into (s,c)
__device__ __forceinline__ void kmerge(float r, float& s, float& c) {
    float y = __fsub_rn(r, c);
    float t = __fadd_rn(s, y);
    c = __fsub_rn(__fsub_rn(t, s), y);
    s = t;
}

__device__ __forceinline__ void kacc2(float a, float b, float& s, float& c) {
    float y = __fmaf_rn(a, b, -c);
    float t = __fadd_rn(s, y);
    c = __fsub_rn(__fsub_rn(t, s), y);
    s = t;
}

__device__ __forceinline__ float sigmoid_exact(float x) {
    return __fdiv_rn(1.0f, __fadd_rn(1.0f, expf(-x)));
}

// ------------------------- bf16 3-way split ---------------------------------
__device__ __forceinline__ void bsplit(float a, __nv_bfloat16& h,
                                       __nv_bfloat16& m, __nv_bfloat16& l) {
    h = __float2bfloat16(a);
    float r1 = __fsub_rn(a, __bfloat162float(h));
    m = __float2bfloat16(r1);
    float r2 = __fsub_rn(r1, __bfloat162float(m));
    l = __float2bfloat16(r2);
}

__global__ void split_a_mlp_kernel(const float* __restrict__ In) {
    int idx = blockIdx.x * blockDim.x + threadIdx.x;
    if (idx >= MROWS * KP1) return;
    int r = idx / KP1, k = idx - r * KP1;
    float v = 0.f;
    if (k < DIN) {
        int b = r / T_STEPS, t = r - b * T_STEPS;
        v = In[b * (DIN * T_STEPS) + k * T_STEPS + t];
    }
    __nv_bfloat16 h, m, l;
    bsplit(v, h, m, l);
    g_Ah[idx] = h; g_Am[idx] = m; g_Al[idx] = l;
}

__global__ void split_a_buf_kernel(int src, int K, int KP) {
    const float* buf = bufsel(src);
    int idx = blockIdx.x * blockDim.x + threadIdx.x;
    if (idx >= MROWS * KP) return;
    int r = idx / KP, k = idx - r * KP;
    float v = (k < K) ? buf[r * K + k] : 0.f;
    __nv_bfloat16 h, m, l;
    bsplit(v, h, m, l);
    g_Ah[idx] = h; g_Am[idx] = m; g_Al[idx] = l;
}

__global__ void split_w_kernel(const float* __restrict__ W, int N, int K, int KP) {
    int idx = blockIdx.x * blockDim.x + threadIdx.x;
    if (idx >= N * KP) return;
    int n = idx / KP, k = idx - n * KP;
    float v = (k < K) ? W[n * K + k] : 0.f;
    __nv_bfloat16 h, m, l;
    bsplit(v, h, m, l);
    g_Wh[idx] = h; g_Wm[idx] = m; g_Wl[idx] = l;
}

// ======================= mma.sync bf16x9 GEMM (chunk-compensated) ===========
__device__ __forceinline__ uint32_t sm2u32(const void* p) {
    uint32_t a;
    asm("{ .reg .u64 t; cvta.to.shared.u64 t, %1; cvt.u32.u64 %0, t; }"
        : "=r"(a) : "l"(p));
    return a;
}

#define LDMX4(r0, r1, r2, r3, addr) \
    asm volatile("ldmatrix.sync.aligned.m8n8.x4.shared.b16 {%0,%1,%2,%3}, [%4];" \
                 : "=r"(r0), "=r"(r1), "=r"(r2), "=r"(r3) : "r"(addr))

#define MMA16816(c, a, b0, b1) \
    asm volatile("mma.sync.aligned.m16n8k16.row.col.f32.bf16.bf16.f32 " \
                 "{%0,%1,%2,%3}, {%4,%5,%6,%7}, {%8,%9}, {%0,%1,%2,%3};" \
                 : "+f"((c)[0]), "+f"((c)[1]), "+f"((c)[2]), "+f"((c)[3]) \
                 : "r"((a)[0]), "r"((a)[1]), "r"((a)[2]), "r"((a)[3]), \
                   "r"(b0), "r"(b1))

__global__ void __launch_bounds__(256) mma_gemm_kernel(
    const float* __restrict__ bias, int csel, int N, int KP) {
    extern __shared__ char smem[];
    float* Cdst = bufsel(csel);
    uint32_t sb = sm2u32(smem);
    int tid = threadIdx.x, w = tid >> 5, lane = tid & 31;
    int m0 = blockIdx.x * 128, n0 = blockIdx.y * 64;

    const __nv_bfloat16* Asrc[3] = {g_Ah, g_Am, g_Al};
    const __nv_bfloat16* Bsrc[3] = {g_Wh, g_Wm, g_Wl};

    // persistent compensated sums
    float ps[8][4], pc[8][4];
#pragma unroll
    for (int i = 0; i < 8; i++)
#pragma unroll
        for (int j = 0; j < 4; j++) { ps[i][j] = 0.f; pc[i][j] = 0.f; }

    int aRow = w * 16 + (lane & 7) + ((lane >> 3) & 1) * 8;
    int aCol = ((lane >> 4) & 1) * 16;
    int bRow = (lane & 7) + ((lane >> 4) & 1) * 8;
    int bCol = ((lane >> 3) & 1) * 16;

    const int nch = KP / 64;
    for (int ch = 0; ch < nch; ch++) {
        const int k0 = ch * 64;
#pragma unroll
        for (int l = 0; l < 12; l++) {
            int e = tid + l * 256;
            int s = e >> 10, rem = e & 1023, m = rem >> 3, j = rem & 7;
            uint4 v = *reinterpret_cast<const uint4*>(
                Asrc[s] + (size_t)(m0 + m) * KP + k0 + j * 8);
            *reinterpret_cast<uint4*>(smem + s * ASPL + m * ROWB + j * 16) = v;
        }
#pragma unroll
        for (int l = 0; l < 6; l++) {
            int e = tid + l * 256;
            int s = e >> 9, rem = e & 511, n = rem >> 3, j = rem & 7;
            uint4 v = make_uint4(0u, 0u, 0u, 0u);
            if (n0 + n < N)
                v = *reinterpret_cast<const uint4*>(
                    Bsrc[s] + (size_t)(n0 + n) * KP + k0 + j * 8);
            *reinterpret_cast<uint4*>(smem + SMEM_B0 + s * BSPL + n * ROWB + j * 16) = v;
        }
        __syncthreads();

        // fresh chunk accumulators
        float acc[8][4];
#pragma unroll
        for (int i = 0; i < 8; i++)
#pragma unroll
            for (int j = 0; j < 4; j++) acc[i][j] = 0.f;

#pragma unroll
        for (int ks = 0; ks < 4; ks++) {
            uint32_t af[3][4];
#pragma unroll
            for (int s = 0; s < 3; s++)
                LDMX4(af[s][0], af[s][1], af[s][2], af[s][3],
                      sb + s * ASPL + aRow * ROWB + ks * 32 + aCol);
#pragma unroll
            for (int q = 0; q < 4; q++) {
                uint32_t bfr[3][4];
#pragma unroll
                for (int s = 0; s < 3; s++)
                    LDMX4(bfr[s][0], bfr[s][1], bfr[s][2], bfr[s][3],
                          sb + SMEM_B0 + s * BSPL + (q * 16 + bRow) * ROWB +
                          ks * 32 + bCol);
                const int pa[9] = {2, 1, 2, 0, 2, 1, 0, 1, 0};
                const int pb[9] = {2, 2, 1, 2, 0, 1, 1, 0, 0};
#pragma unroll
                for (int p = 0; p < 9; p++) {
                    MMA16816(acc[2 * q],     af[pa[p]], bfr[pb[p]][0], bfr[pb[p]][1]);
                    MMA16816(acc[2 * q + 1], af[pa[p]], bfr[pb[p]][2], bfr[pb[p]][3]);
                }
            }
        }
        // compensated merge of chunk sums into persistent (ps, pc)
#pragma unroll
        for (int i = 0; i < 8; i++)
#pragma unroll
            for (int j = 0; j < 4; j++) kmerge(acc[i][j], ps[i][j], pc[i][j]);
        __syncthreads();
    }

    int r = lane >> 2, cp = (lane & 3) * 2;
#pragma unroll
    for (int nb = 0; nb < 8; nb++) {
        int n = n0 + nb * 8 + cp;
        int m = m0 + w * 16 + r;
        if (n < N) {
            Cdst[(size_t)m * N + n] =
                __fadd_rn(__fsub_rn(ps[nb][0], pc[nb][0]), bias[n]);
            Cdst[(size_t)(m + 8) * N + n] =
                __fadd_rn(__fsub_rn(ps[nb][2], pc[nb][2]), bias[n]);
        }
        if (n + 1 < N) {
            Cdst[(size_t)m * N + n + 1] =
                __fadd_rn(__fsub_rn(ps[nb][1], pc[nb][1]), bias[n + 1]);
            Cdst[(size_t)(m + 8) * N + n + 1] =
                __fadd_rn(__fsub_rn(ps[nb][3], pc[nb][3]), bias[n + 1]);
        }
    }
}

// ------------------------- BN stats: single pass fp64 sum + sumsq -----------
__global__ void bn_stats_kernel() {
    int blk = blockIdx.x;
    int tid = threadIdx.x;
    double ls[4] = {0.0, 0.0, 0.0, 0.0};
    double lq[4] = {0.0, 0.0, 0.0, 0.0};
    int r0 = blk * (MROWS / NSTATB);
    for (int r = r0; r < r0 + (MROWS / NSTATB); r++) {
        const float* row = g_buf0 + r * DIN;
#pragma unroll
        for (int j = 0; j < 4; j++) {
            int c = tid + j * 256;
            if (c < DIN) {
                double v = (double)row[c];
                ls[j] += v;
                lq[j] += v * v;
            }
        }
    }
#pragma unroll
    for (int j = 0; j < 4; j++) {
        int c = tid + j * 256;
        if (c < DIN) {
            g_psumd[blk * DIN + c] = ls[j];
            g_psqd [blk * DIN + c] = lq[j];
        }
    }
}

__global__ void bn_fin_kernel() {
    int c = blockIdx.x * blockDim.x + threadIdx.x;
    if (c >= DIN) return;
    double s = 0.0, q = 0.0;
    for (int i = 0; i < NSTATB; i++) {
        s += g_psumd[i * DIN + c];
        q += g_psqd [i * DIN + c];
    }
    float sumf = (float)s;
    g_mean[c] = __fdiv_rn(sumf, (float)MROWS);
    double meand = s / (double)MROWS;
    double vard = q / (double)MROWS - meand * meand;
    float var = (float)vard;
    g_rs[c] = rsqrtf(__fadd_rn(var, EPS_BN));
}

// ------------------------- fused BN apply + sigmoid + axon1 (in place) ------
__global__ void axon1_bn_kernel(const float* __restrict__ gamma,
                                const float* __restrict__ beta,
                                const float* __restrict__ a1,
                                const float* __restrict__ a2) {
    int idx = blockIdx.x * blockDim.x + threadIdx.x;
    if (idx >= BATCH * DIN) return;
    int b = idx / DIN, c = idx - b * DIN;
    float A1 = a1[c], A2 = a2[c];
    float mean = g_mean[c], rs = g_rs[c], gm = gamma[c], bt = beta[c];
    float p1 = 0.f, p2 = 0.f;
    int off = b * T_STEPS * DIN + c;
    for (int t = 0; t < T_STEPS; t++, off += DIN) {
        float v = __fsub_rn(g_buf0[off], mean);
        v = __fmul_rn(gm, v);
        v = __fmul_rn(v, rs);
        v = __fadd_rn(v, bt);
        float x = sigmoid_exact(v);
        float p = __fadd_rn(__fadd_rn(__fmul_rn(A1, p1), __fmul_rn(A2, p2)), x);
        g_buf0[off] = p;
        p2 = p1;
        p1 = p;
    }
}

// -------- fused LIF (layer l) + dropout mask + axon (layer l+1), in place ---
__global__ void lif_axon_kernel(int bsel, const float* __restrict__ mask,
                                const float* __restrict__ a1,
                                const float* __restrict__ a2) {
    float* buf = bufsel(bsel);
    int idx = blockIdx.x * blockDim.x + threadIdx.x;
    if (idx >= BATCH * HID) return;
    int b = idx / HID, cch = idx - b * HID;
    float A1 = a1[cch], A2 = a2[cch];
    float v = 0.f, sp = 0.f;
    float p1 = 0.f, p2 = 0.f;
    int off = b * T_STEPS * HID + cch;
    int moff = (b * HID + cch) * T_STEPS;
    for (int t = 0; t < T_STEPS; t++, off += HID) {
        float z = buf[off];
        v = __fadd_rn(__fmul_rn(__fmul_rn(DECAY_M, v), __fsub_rn(1.0f, sp)), z);
        sp = (v > 1.0f) ? 1.0f : 0.0f;
        float x = __fmul_rn(sp, mask[moff + t]);
        float p = __fadd_rn(__fadd_rn(__fmul_rn(A1, p1), __fmul_rn(A2, p2)), x);
        buf[off] = p;
        p2 = p1;
        p1 = p;
    }
}

// ------------------------- GEMM3 (N=10): compensated ------------------------
__global__ void __launch_bounds__(256) gemm3_kernel(
    const float* __restrict__ W3, const float* __restrict__ b3) {
    __shared__ float sW[NOUT][HID];
    int tid = threadIdx.x;
    for (int i = tid; i < NOUT * HID; i += 256) sW[i / HID][i % HID] = W3[i];
    __syncthreads();
    int idx = blockIdx.x * 256 + tid;
    int r = idx / NOUT, o = idx - r * NOUT;
    const float* a = g_buf2 + r * HID;
    float s = 0.f, c = 0.f;
    for (int k = 0; k < HID; k++) kacc2(a[k], sW[o][k], s, c);
    float acc = __fsub_rn(s, c);
    g_buf3[r * NOUT + o] = __fadd_rn(acc, b3[o]);
}

// ------------------------- final LIF + output transpose [B,10,T] ------------
__global__ void lif3_out_kernel(float* __restrict__ out) {
    int idx = blockIdx.x * blockDim.x + threadIdx.x;
    if (idx >= BATCH * NOUT) return;
    int b = idx / NOUT, o = idx - b * NOUT;
    float v = 0.f, s = 0.f;
    for (int t = 0; t < T_STEPS; t++) {
        float z = g_buf3[(b * T_STEPS + t) * NOUT + o];
        v = __fadd_rn(__fmul_rn(__fmul_rn(DECAY_M, v), __fsub_rn(1.0f, s)), z);
        s = (v > 1.0f) ? 1.0f : 0.0f;
        out[(b * NOUT + o) * T_STEPS + t] = s;
    }
}

// ------------------------- launch -------------------------------------------
extern "C" void kernel_launch(void* const* d_in, const int* in_sizes, int n_in,
                              void* d_out, int out_size) {
    const float* inputs = (const float*)d_in[0];
    const float* W_mlp  = (const float*)d_in[1];
    const float* b_mlp  = (const float*)d_in[2];
    const float* gamma  = (const float*)d_in[3];
    const float* beta   = (const float*)d_in[4];
    const float* a1_1   = (const float*)d_in[5];
    const float* a2_1   = (const float*)d_in[6];
    const float* W1     = (const float*)d_in[7];
    const float* b1     = (const float*)d_in[8];
    const float* a1_2   = (const float*)d_in[9];
    const float* a2_2   = (const float*)d_in[10];
    const float* W2     = (const float*)d_in[11];
    const float* b2     = (const float*)d_in[12];
    const float* a1_3   = (const float*)d_in[13];
    const float* a2_3   = (const float*)d_in[14];
    const float* W3     = (const float*)d_in[15];
    const float* b3     = (const float*)d_in[16];
    const float* mask1  = (const float*)d_in[17];
    const float* mask2  = (const float*)d_in[18];
    float* out = (float*)d_out;

    static int smem_set = 0;
    if (!smem_set) {
        cudaFuncSetAttribute(mma_gemm_kernel,
                             cudaFuncAttributeMaxDynamicSharedMemorySize, SMEM_TOT);
        smem_set = 1;
    }

    split_a_mlp_kernel<<<(MROWS * KP1 + 255) / 256, 256>>>(inputs);
    split_w_kernel<<<(DIN * KP1 + 255) / 256, 256>>>(W_mlp, DIN, DIN, KP1);
    mma_gemm_kernel<<<dim3(MROWS / 128, (DIN + 63) / 64), 256, SMEM_TOT>>>(
        b_mlp, 0, DIN, KP1);

    bn_stats_kernel<<<NSTATB, 256>>>();
    bn_fin_kernel<<<(DIN + 255) / 256, 256>>>();
    axon1_bn_kernel<<<(BATCH * DIN + 255) / 256, 256>>>(gamma, beta, a1_1, a2_1);

    split_a_buf_kernel<<<(MROWS * KP1 + 255) / 256, 256>>>(0, DIN, KP1);
    split_w_kernel<<<(HID * KP1 + 255) / 256, 256>>>(W1, HID, DIN, KP1);
    mma_gemm_kernel<<<dim3(MROWS / 128, (HID + 63) / 64), 256, SMEM_TOT>>>(
        b1, 1, HID, KP1);
    lif_axon_kernel<<<(BATCH * HID + 255) / 256, 256>>>(1, mask1, a1_2, a2_2);

    split_a_buf_kernel<<<(MROWS * KP2 + 255) / 256, 256>>>(1, HID, KP2);
    split_w_kernel<<<(HID * KP2 + 255) / 256, 256>>>(W2, HID, HID, KP2);
    mma_gemm_kernel<<<dim3(MROWS / 128, (HID + 63) / 64), 256, SMEM_TOT>>>(
        b2, 2, HID, KP2);
    lif_axon_kernel<<<(BATCH * HID + 255) / 256, 256>>>(2, mask2, a1_3, a2_3);

    gemm3_kernel<<<MROWS * NOUT / 256, 256>>>(W3, b3);
    lif3_out_kernel<<<(BATCH * NOUT + 255) / 256, 256>>>(out);
}

// round 14
// speedup vs baseline: 2.2984x; 1.1588x over previous
#include <cuda_runtime.h>
#include <cuda_bf16.h>
#include <math.h>
#include <stdint.h>

#define T_STEPS 200
#define BATCH   128
#define DIN     784
#define HID     500
#define NOUT    10
#define MROWS   (BATCH * T_STEPS)   // 25600
#define DECAY_M 0.77880078307140487f
#define EPS_BN  1e-5f
#define NSTATB  800
#define KP1     832
#define KP2     512

#define ROWB    144
#define ASPL    (128 * ROWB)
#define BSPL    (64 * ROWB)
#define SMEM_B0 (3 * ASPL)
#define SMEM_TOT (SMEM_B0 + 3 * BSPL)   // 82944

// ------------------------- device scratch (no allocs allowed) ---------------
__device__ float g_buf0[MROWS * DIN];
__device__ float g_buf1[MROWS * HID];
__device__ float g_buf2[MROWS * HID];
__device__ float g_buf3[MROWS * NOUT];
__device__ double g_psumd[NSTATB * DIN];
__device__ double g_psqd [NSTATB * DIN];
__device__ float g_mean[DIN];
__device__ float g_rs[DIN];
__device__ __nv_bfloat16 g_Ah[MROWS * KP1];
__device__ __nv_bfloat16 g_Am[MROWS * KP1];
__device__ __nv_bfloat16 g_Al[MROWS * KP1];
__device__ __nv_bfloat16 g_Wh[800 * KP1];
__device__ __nv_bfloat16 g_Wm[800 * KP1];
__device__ __nv_bfloat16 g_Wl[800 * KP1];

__device__ __forceinline__ float* bufsel(int s) {
    return s == 0 ? g_buf0 : (s == 1 ? g_buf1 : g_buf2);
}

__device__ __forceinline__ void kmerge(float r, float& s, float& c) {
    float y = __fsub_rn(r, c);
    float t = __fadd_rn(s, y);
    c = __fsub_rn(__fsub_rn(t, s), y);
    s = t;
}

__device__ __forceinline__ void kacc2(float a, float b, float& s, float& c) {
    float y = __fmaf_rn(a, b, -c);
    float t = __fadd_rn(s, y);
    c = __fsub_rn(__fsub_rn(t, s), y);
    s = t;
}

__device__ __forceinline__ float sigmoid_exact(float x) {
    return __fdiv_rn(1.0f, __fadd_rn(1.0f, expf(-x)));
}

// ------------------------- bf16 3-way split ---------------------------------
__device__ __forceinline__ void bsplit(float a, __nv_bfloat16& h,
                                       __nv_bfloat16& m, __nv_bfloat16& l) {
    h = __float2bfloat16(a);
    float r1 = __fsub_rn(a, __bfloat162float(h));
    m = __float2bfloat16(r1);
    float r2 = __fsub_rn(r1, __bfloat162float(m));
    l = __float2bfloat16(r2);
}

__global__ void split_a_mlp_kernel(const float* __restrict__ In) {
    int idx = blockIdx.x * blockDim.x + threadIdx.x;
    if (idx >= MROWS * KP1) return;
    int r = idx / KP1, k = idx - r * KP1;
    float v = 0.f;
    if (k < DIN) {
        int b = r / T_STEPS, t = r - b * T_STEPS;
        v = In[b * (DIN * T_STEPS) + k * T_STEPS + t];
    }
    __nv_bfloat16 h, m, l;
    bsplit(v, h, m, l);
    g_Ah[idx] = h; g_Am[idx] = m; g_Al[idx] = l;
}

__global__ void split_w_kernel(const float* __restrict__ W, int N, int K, int KP) {
    int idx = blockIdx.x * blockDim.x + threadIdx.x;
    if (idx >= N * KP) return;
    int n = idx / KP, k = idx - n * KP;
    float v = (k < K) ? W[n * K + k] : 0.f;
    __nv_bfloat16 h, m, l;
    bsplit(v, h, m, l);
    g_Wh[idx] = h; g_Wm[idx] = m; g_Wl[idx] = l;
}

// zero KP2 pad columns (alias stale KP1-layout data each replay)
__global__ void zero_pad2_kernel() {
    int idx = blockIdx.x * blockDim.x + threadIdx.x;
    if (idx >= MROWS * (KP2 - HID)) return;
    int r = idx / (KP2 - HID), j = idx - r * (KP2 - HID);
    int off = r * KP2 + HID + j;
    g_Ah[off] = __float2bfloat16(0.f);
    g_Am[off] = __float2bfloat16(0.f);
    g_Al[off] = __float2bfloat16(0.f);
}

// ======================= mma.sync bf16x6 GEMM (chunk-compensated) ===========
__device__ __forceinline__ uint32_t sm2u32(const void* p) {
    uint32_t a;
    asm("{ .reg .u64 t; cvta.to.shared.u64 t, %1; cvt.u32.u64 %0, t; }"
        : "=r"(a) : "l"(p));
    return a;
}

#define LDMX4(r0, r1, r2, r3, addr) \
    asm volatile("ldmatrix.sync.aligned.m8n8.x4.shared.b16 {%0,%1,%2,%3}, [%4];" \
                 : "=r"(r0), "=r"(r1), "=r"(r2), "=r"(r3) : "r"(addr))

#define MMA16816(c, a, b0, b1) \
    asm volatile("mma.sync.aligned.m16n8k16.row.col.f32.bf16.bf16.f32 " \
                 "{%0,%1,%2,%3}, {%4,%5,%6,%7}, {%8,%9}, {%0,%1,%2,%3};" \
                 : "+f"((c)[0]), "+f"((c)[1]), "+f"((c)[2]), "+f"((c)[3]) \
                 : "r"((a)[0]), "r"((a)[1]), "r"((a)[2]), "r"((a)[3]), \
                   "r"(b0), "r"(b1))

__global__ void __launch_bounds__(256) mma_gemm_kernel(
    const float* __restrict__ bias, int csel, int N, int KP) {
    extern __shared__ char smem[];
    float* Cdst = bufsel(csel);
    uint32_t sb = sm2u32(smem);
    int tid = threadIdx.x, w = tid >> 5, lane = tid & 31;
    int m0 = blockIdx.x * 128, n0 = blockIdx.y * 64;

    const __nv_bfloat16* Asrc[3] = {g_Ah, g_Am, g_Al};
    const __nv_bfloat16* Bsrc[3] = {g_Wh, g_Wm, g_Wl};

    float ps[8][4], pc[8][4];
#pragma unroll
    for (int i = 0; i < 8; i++)
#pragma unroll
        for (int j = 0; j < 4; j++) { ps[i][j] = 0.f; pc[i][j] = 0.f; }

    int aRow = w * 16 + (lane & 7) + ((lane >> 3) & 1) * 8;
    int aCol = ((lane >> 4) & 1) * 16;
    int bRow = (lane & 7) + ((lane >> 4) & 1) * 8;
    int bCol = ((lane >> 3) & 1) * 16;

    const int nch = KP / 64;
    for (int ch = 0; ch < nch; ch++) {
        const int k0 = ch * 64;
#pragma unroll
        for (int l = 0; l < 12; l++) {
            int e = tid + l * 256;
            int s = e >> 10, rem = e & 1023, m = rem >> 3, j = rem & 7;
            uint4 v = *reinterpret_cast<const uint4*>(
                Asrc[s] + (size_t)(m0 + m) * KP + k0 + j * 8);
            *reinterpret_cast<uint4*>(smem + s * ASPL + m * ROWB + j * 16) = v;
        }
#pragma unroll
        for (int l = 0; l < 6; l++) {
            int e = tid + l * 256;
            int s = e >> 9, rem = e & 511, n = rem >> 3, j = rem & 7;
            uint4 v = make_uint4(0u, 0u, 0u, 0u);
            if (n0 + n < N)
                v = *reinterpret_cast<const uint4*>(
                    Bsrc[s] + (size_t)(n0 + n) * KP + k0 + j * 8);
            *reinterpret_cast<uint4*>(smem + SMEM_B0 + s * BSPL + n * ROWB + j * 16) = v;
        }
        __syncthreads();

        float acc[8][4];
#pragma unroll
        for (int i = 0; i < 8; i++)
#pragma unroll
            for (int j = 0; j < 4; j++) acc[i][j] = 0.f;

#pragma unroll
        for (int ks = 0; ks < 4; ks++) {
            uint32_t af[3][4];
#pragma unroll
            for (int s = 0; s < 3; s++)
                LDMX4(af[s][0], af[s][1], af[s][2], af[s][3],
                      sb + s * ASPL + aRow * ROWB + ks * 32 + aCol);
#pragma unroll
            for (int q = 0; q < 4; q++) {
                uint32_t bfr[3][4];
#pragma unroll
                for (int s = 0; s < 3; s++)
                    LDMX4(bfr[s][0], bfr[s][1], bfr[s][2], bfr[s][3],
                          sb + SMEM_B0 + s * BSPL + (q * 16 + bRow) * ROWB +
                          ks * 32 + bCol);
                // bf16x6: hl, lh, mm, hm, mh, hh (ascending magnitude)
                const int pa[6] = {0, 2, 1, 0, 1, 0};
                const int pb[6] = {2, 0, 1, 1, 0, 0};
#pragma unroll
                for (int p = 0; p < 6; p++) {
                    MMA16816(acc[2 * q],     af[pa[p]], bfr[pb[p]][0], bfr[pb[p]][1]);
                    MMA16816(acc[2 * q + 1], af[pa[p]], bfr[pb[p]][2], bfr[pb[p]][3]);
                }
            }
        }
#pragma unroll
        for (int i = 0; i < 8; i++)
#pragma unroll
            for (int j = 0; j < 4; j++) kmerge(acc[i][j], ps[i][j], pc[i][j]);
        __syncthreads();
    }

    int r = lane >> 2, cp = (lane & 3) * 2;
#pragma unroll
    for (int nb = 0; nb < 8; nb++) {
        int n = n0 + nb * 8 + cp;
        int m = m0 + w * 16 + r;
        if (n < N) {
            Cdst[(size_t)m * N + n] =
                __fadd_rn(__fsub_rn(ps[nb][0], pc[nb][0]), bias[n]);
            Cdst[(size_t)(m + 8) * N + n] =
                __fadd_rn(__fsub_rn(ps[nb][2], pc[nb][2]), bias[n]);
        }
        if (n + 1 < N) {
            Cdst[(size_t)m * N + n + 1] =
                __fadd_rn(__fsub_rn(ps[nb][1], pc[nb][1]), bias[n + 1]);
            Cdst[(size_t)(m + 8) * N + n + 1] =
                __fadd_rn(__fsub_rn(ps[nb][3], pc[nb][3]), bias[n + 1]);
        }
    }
}

// ------------------------- BN stats: single pass fp64 sum + sumsq -----------
__global__ void bn_stats_kernel() {
    int blk = blockIdx.x;
    int tid = threadIdx.x;
    double ls[4] = {0.0, 0.0, 0.0, 0.0};
    double lq[4] = {0.0, 0.0, 0.0, 0.0};
    int r0 = blk * (MROWS / NSTATB);
    for (int r = r0; r < r0 + (MROWS / NSTATB); r++) {
        const float* row = g_buf0 + r * DIN;
#pragma unroll
        for (int j = 0; j < 4; j++) {
            int c = tid + j * 256;
            if (c < DIN) {
                double v = (double)row[c];
                ls[j] += v;
                lq[j] += v * v;
            }
        }
    }
#pragma unroll
    for (int j = 0; j < 4; j++) {
        int c = tid + j * 256;
        if (c < DIN) {
            g_psumd[blk * DIN + c] = ls[j];
            g_psqd [blk * DIN + c] = lq[j];
        }
    }
}

__global__ void bn_fin_kernel() {
    int c = blockIdx.x * blockDim.x + threadIdx.x;
    if (c >= DIN) return;
    double s = 0.0, q = 0.0;
    for (int i = 0; i < NSTATB; i++) {
        s += g_psumd[i * DIN + c];
        q += g_psqd [i * DIN + c];
    }
    float sumf = (float)s;
    g_mean[c] = __fdiv_rn(sumf, (float)MROWS);
    double meand = s / (double)MROWS;
    double vard = q / (double)MROWS - meand * meand;
    float var = (float)vard;
    g_rs[c] = rsqrtf(__fadd_rn(var, EPS_BN));
}

// ------- fused BN apply + sigmoid + axon1, writes bf16x3 splits (KP1) -------
__global__ void axon1_bn_split_kernel(const float* __restrict__ gamma,
                                      const float* __restrict__ beta,
                                      const float* __restrict__ a1,
                                      const float* __restrict__ a2) {
    int idx = blockIdx.x * blockDim.x + threadIdx.x;
    if (idx >= BATCH * DIN) return;
    int b = idx / DIN, c = idx - b * DIN;
    float A1 = a1[c], A2 = a2[c];
    float mean = g_mean[c], rs = g_rs[c], gm = gamma[c], bt = beta[c];
    float p1 = 0.f, p2 = 0.f;
    int off = b * T_STEPS * DIN + c;
    int soff = b * T_STEPS * KP1 + c;
    for (int t = 0; t < T_STEPS; t++, off += DIN, soff += KP1) {
        float v = __fsub_rn(g_buf0[off], mean);
        v = __fmul_rn(gm, v);
        v = __fmul_rn(v, rs);
        v = __fadd_rn(v, bt);
        float x = sigmoid_exact(v);
        float p = __fadd_rn(__fadd_rn(__fmul_rn(A1, p1), __fmul_rn(A2, p2)), x);
        __nv_bfloat16 h, m, l;
        bsplit(p, h, m, l);
        g_Ah[soff] = h; g_Am[soff] = m; g_Al[soff] = l;
        p2 = p1;
        p1 = p;
    }
}

// ---- fused LIF + mask + axon, writes bf16x3 splits (KP2 layout) ------------
__global__ void lif_axon_split_kernel(int bsel, const float* __restrict__ mask,
                                      const float* __restrict__ a1,
                                      const float* __restrict__ a2) {
    float* buf = bufsel(bsel);
    int idx = blockIdx.x * blockDim.x + threadIdx.x;
    if (idx >= BATCH * HID) return;
    int b = idx / HID, cch = idx - b * HID;
    float A1 = a1[cch], A2 = a2[cch];
    float v = 0.f, sp = 0.f;
    float p1 = 0.f, p2 = 0.f;
    int off = b * T_STEPS * HID + cch;
    int soff = b * T_STEPS * KP2 + cch;
    int moff = (b * HID + cch) * T_STEPS;
    for (int t = 0; t < T_STEPS; t++, off += HID, soff += KP2) {
        float z = buf[off];
        v = __fadd_rn(__fmul_rn(__fmul_rn(DECAY_M, v), __fsub_rn(1.0f, sp)), z);
        sp = (v > 1.0f) ? 1.0f : 0.0f;
        float x = __fmul_rn(sp, mask[moff + t]);
        float p = __fadd_rn(__fadd_rn(__fmul_rn(A1, p1), __fmul_rn(A2, p2)), x);
        __nv_bfloat16 h, m, l;
        bsplit(p, h, m, l);
        g_Ah[soff] = h; g_Am[soff] = m; g_Al[soff] = l;
        p2 = p1;
        p1 = p;
    }
}

// ---- fused LIF + mask + axon, writes fp32 buf (feeds fp32 gemm3) -----------
__global__ void lif_axon_kernel(int bsel, const float* __restrict__ mask,
                                const float* __restrict__ a1,
                                const float* __restrict__ a2) {
    float* buf = bufsel(bsel);
    int idx = blockIdx.x * blockDim.x + threadIdx.x;
    if (idx >= BATCH * HID) return;
    int b = idx / HID, cch = idx - b * HID;
    float A1 = a1[cch], A2 = a2[cch];
    float v = 0.f, sp = 0.f;
    float p1 = 0.f, p2 = 0.f;
    int off = b * T_STEPS * HID + cch;
    int moff = (b * HID + cch) * T_STEPS;
    for (int t = 0; t < T_STEPS; t++, off += HID) {
        float z = buf[off];
        v = __fadd_rn(__fmul_rn(__fmul_rn(DECAY_M, v), __fsub_rn(1.0f, sp)), z);
        sp = (v > 1.0f) ? 1.0f : 0.0f;
        float x = __fmul_rn(sp, mask[moff + t]);
        float p = __fadd_rn(__fadd_rn(__fmul_rn(A1, p1), __fmul_rn(A2, p2)), x);
        buf[off] = p;
        p2 = p1;
        p1 = p;
    }
}

// ------------------------- GEMM3 (N=10): compensated ------------------------
__global__ void __launch_bounds__(256) gemm3_kernel(
    const float* __restrict__ W3, const float* __restrict__ b3) {
    __shared__ float sW[NOUT][HID];
    int tid = threadIdx.x;
    for (int i = tid; i < NOUT * HID; i += 256) sW[i / HID][i % HID] = W3[i];
    __syncthreads();
    int idx = blockIdx.x * 256 + tid;
    int r = idx / NOUT, o = idx - r * NOUT;
    const float* a = g_buf2 + r * HID;
    float s = 0.f, c = 0.f;
    for (int k = 0; k < HID; k++) kacc2(a[k], sW[o][k], s, c);
    float acc = __fsub_rn(s, c);
    g_buf3[r * NOUT + o] = __fadd_rn(acc, b3[o]);
}

// ------------------------- final LIF + output transpose [B,10,T] ------------
__global__ void lif3_out_kernel(float* __restrict__ out) {
    int idx = blockIdx.x * blockDim.x + threadIdx.x;
    if (idx >= BATCH * NOUT) return;
    int b = idx / NOUT, o = idx - b * NOUT;
    float v = 0.f, s = 0.f;
    for (int t = 0; t < T_STEPS; t++) {
        float z = g_buf3[(b * T_STEPS + t) * NOUT + o];
        v = __fadd_rn(__fmul_rn(__fmul_rn(DECAY_M, v), __fsub_rn(1.0f, s)), z);
        s = (v > 1.0f) ? 1.0f : 0.0f;
        out[(b * NOUT + o) * T_STEPS + t] = s;
    }
}

// ------------------------- launch -------------------------------------------
extern "C" void kernel_launch(void* const* d_in, const int* in_sizes, int n_in,
                              void* d_out, int out_size) {
    const float* inputs = (const float*)d_in[0];
    const float* W_mlp  = (const float*)d_in[1];
    const float* b_mlp  = (const float*)d_in[2];
    const float* gamma  = (const float*)d_in[3];
    const float* beta   = (const float*)d_in[4];
    const float* a1_1   = (const float*)d_in[5];
    const float* a2_1   = (const float*)d_in[6];
    const float* W1     = (const float*)d_in[7];
    const float* b1     = (const float*)d_in[8];
    const float* a1_2   = (const float*)d_in[9];
    const float* a2_2   = (const float*)d_in[10];
    const float* W2     = (const float*)d_in[11];
    const float* b2     = (const float*)d_in[12];
    const float* a1_3   = (const float*)d_in[13];
    const float* a2_3   = (const float*)d_in[14];
    const float* W3     = (const float*)d_in[15];
    const float* b3     = (const float*)d_in[16];
    const float* mask1  = (const float*)d_in[17];
    const float* mask2  = (const float*)d_in[18];
    float* out = (float*)d_out;

    static int smem_set = 0;
    if (!smem_set) {
        cudaFuncSetAttribute(mma_gemm_kernel,
                             cudaFuncAttributeMaxDynamicSharedMemorySize, SMEM_TOT);
        smem_set = 1;
    }

    // ---- GEMM MLP
    split_a_mlp_kernel<<<(MROWS * KP1 + 255) / 256, 256>>>(inputs);
    split_w_kernel<<<(DIN * KP1 + 255) / 256, 256>>>(W_mlp, DIN, DIN, KP1);
    mma_gemm_kernel<<<dim3(MROWS / 128, (DIN + 63) / 64), 256, SMEM_TOT>>>(
        b_mlp, 0, DIN, KP1);

    bn_stats_kernel<<<NSTATB, 256>>>();
    bn_fin_kernel<<<(DIN + 255) / 256, 256>>>();
    axon1_bn_split_kernel<<<(BATCH * DIN + 255) / 256, 256>>>(gamma, beta, a1_1, a2_1);

    // ---- GEMM1
    split_w_kernel<<<(HID * KP1 + 255) / 256, 256>>>(W1, HID, DIN, KP1);
    mma_gemm_kernel<<<dim3(MROWS / 128, (HID + 63) / 64), 256, SMEM_TOT>>>(
        b1, 1, HID, KP1);
    lif_axon_split_kernel<<<(BATCH * HID + 255) / 256, 256>>>(1, mask1, a1_2, a2_2);
    zero_pad2_kernel<<<(MROWS * (KP2 - HID) + 255) / 256, 256>>>();

    // ---- GEMM2
    split_w_kernel<<<(HID * KP2 + 255) / 256, 256>>>(W2, HID, HID, KP2);
    mma_gemm_kernel<<<dim3(MROWS / 128, (HID + 63) / 64), 256, SMEM_TOT>>>(
        b2, 2, HID, KP2);
    lif_axon_kernel<<<(BATCH * HID + 255) / 256, 256>>>(2, mask2, a1_3, a2_3);

    // ---- GEMM3 + output
    gemm3_kernel<<<MROWS * NOUT / 256, 256>>>(W3, b3);
    lif3_out_kernel<<<(BATCH * NOUT + 255) / 256, 256>>>(out);
}

// round 15
// speedup vs baseline: 2.3014x; 1.0013x over previous
#include <cuda_runtime.h>
#include <cuda_bf16.h>
#include <math.h>
#include <stdint.h>

#define T_STEPS 200
#define BATCH   128
#define DIN     784
#define HID     500
#define NOUT    10
#define MROWS   (BATCH * T_STEPS)   // 25600
#define DECAY_M 0.77880078307140487f
#define EPS_BN  1e-5f
#define NSTATB  800
#define KP1     832
#define KP2     512

#define ROWB    144
#define ASPL    (128 * ROWB)
#define BSPL    (64 * ROWB)
#define SMEM_B0 (3 * ASPL)
#define SMEM_TOT (SMEM_B0 + 3 * BSPL)   // 82944

// ------------------------- device scratch (no allocs allowed) ---------------
__device__ float g_buf0[MROWS * DIN];
__device__ float g_buf1[MROWS * HID];
__device__ float g_buf2[MROWS * HID];
__device__ float g_buf3[MROWS * NOUT];
__device__ double g_psumd[NSTATB * DIN];
__device__ double g_psqd [NSTATB * DIN];
__device__ float g_mean[DIN];
__device__ float g_rs[DIN];
__device__ __nv_bfloat16 g_Ah[MROWS * KP1];
__device__ __nv_bfloat16 g_Am[MROWS * KP1];
__device__ __nv_bfloat16 g_Al[MROWS * KP1];
__device__ __nv_bfloat16 g_Wh[800 * KP1];
__device__ __nv_bfloat16 g_Wm[800 * KP1];
__device__ __nv_bfloat16 g_Wl[800 * KP1];

__device__ __forceinline__ float* bufsel(int s) {
    return s == 0 ? g_buf0 : (s == 1 ? g_buf1 : g_buf2);
}

__device__ __forceinline__ void kmerge(float r, float& s, float& c) {
    float y = __fsub_rn(r, c);
    float t = __fadd_rn(s, y);
    c = __fsub_rn(__fsub_rn(t, s), y);
    s = t;
}

__device__ __forceinline__ void kacc2(float a, float b, float& s, float& c) {
    float y = __fmaf_rn(a, b, -c);
    float t = __fadd_rn(s, y);
    c = __fsub_rn(__fsub_rn(t, s), y);
    s = t;
}

__device__ __forceinline__ float sigmoid_exact(float x) {
    return __fdiv_rn(1.0f, __fadd_rn(1.0f, expf(-x)));
}

// ------------------------- bf16 3-way split ---------------------------------
__device__ __forceinline__ void bsplit(float a, __nv_bfloat16& h,
                                       __nv_bfloat16& m, __nv_bfloat16& l) {
    h = __float2bfloat16(a);
    float r1 = __fsub_rn(a, __bfloat162float(h));
    m = __float2bfloat16(r1);
    float r2 = __fsub_rn(r1, __bfloat162float(m));
    l = __float2bfloat16(r2);
}

// ---- coalesced tiled split of inputs [B, DIN, T] -> split rows (b*T+t, k) --
__global__ void split_a_mlp_t_kernel(const float* __restrict__ In) {
    __shared__ float tile[32][33];
    int b  = blockIdx.x;
    int t0 = blockIdx.y * 32;
    int k0 = blockIdx.z * 32;
#pragma unroll
    for (int i = 0; i < 4; i++) {
        int k = k0 + threadIdx.y + i * 8;
        int t = t0 + threadIdx.x;
        float v = 0.f;
        if (k < DIN && t < T_STEPS)
            v = In[b * (DIN * T_STEPS) + k * T_STEPS + t];
        tile[threadIdx.y + i * 8][threadIdx.x] = v;
    }
    __syncthreads();
#pragma unroll
    for (int i = 0; i < 4; i++) {
        int t = t0 + threadIdx.y + i * 8;
        int k = k0 + threadIdx.x;
        if (t < T_STEPS) {   // k < 832 always (26 * 32 = 832)
            float v = tile[threadIdx.x][threadIdx.y + i * 8];
            __nv_bfloat16 h, m, l;
            bsplit(v, h, m, l);
            int soff = (b * T_STEPS + t) * KP1 + k;
            g_Ah[soff] = h; g_Am[soff] = m; g_Al[soff] = l;
        }
    }
}

__global__ void split_w_kernel(const float* __restrict__ W, int N, int K, int KP) {
    int idx = blockIdx.x * blockDim.x + threadIdx.x;
    if (idx >= N * KP) return;
    int n = idx / KP, k = idx - n * KP;
    float v = (k < K) ? W[n * K + k] : 0.f;
    __nv_bfloat16 h, m, l;
    bsplit(v, h, m, l);
    g_Wh[idx] = h; g_Wm[idx] = m; g_Wl[idx] = l;
}

// zero KP2 pad columns (alias stale KP1-layout data each replay)
__global__ void zero_pad2_kernel() {
    int idx = blockIdx.x * blockDim.x + threadIdx.x;
    if (idx >= MROWS * (KP2 - HID)) return;
    int r = idx / (KP2 - HID), j = idx - r * (KP2 - HID);
    int off = r * KP2 + HID + j;
    g_Ah[off] = __float2bfloat16(0.f);
    g_Am[off] = __float2bfloat16(0.f);
    g_Al[off] = __float2bfloat16(0.f);
}

// ======================= mma.sync bf16x6 GEMM (chunk-compensated) ===========
__device__ __forceinline__ uint32_t sm2u32(const void* p) {
    uint32_t a;
    asm("{ .reg .u64 t; cvta.to.shared.u64 t, %1; cvt.u32.u64 %0, t; }"
        : "=r"(a) : "l"(p));
    return a;
}

#define LDMX4(r0, r1, r2, r3, addr) \
    asm volatile("ldmatrix.sync.aligned.m8n8.x4.shared.b16 {%0,%1,%2,%3}, [%4];" \
                 : "=r"(r0), "=r"(r1), "=r"(r2), "=r"(r3) : "r"(addr))

#define MMA16816(c, a, b0, b1) \
    asm volatile("mma.sync.aligned.m16n8k16.row.col.f32.bf16.bf16.f32 " \
                 "{%0,%1,%2,%3}, {%4,%5,%6,%7}, {%8,%9}, {%0,%1,%2,%3};" \
                 : "+f"((c)[0]), "+f"((c)[1]), "+f"((c)[2]), "+f"((c)[3]) \
                 : "r"((a)[0]), "r"((a)[1]), "r"((a)[2]), "r"((a)[3]), \
                   "r"(b0), "r"(b1))

__global__ void __launch_bounds__(256) mma_gemm_kernel(
    const float* __restrict__ bias, int csel, int N, int KP) {
    extern __shared__ char smem[];
    float* Cdst = bufsel(csel);
    uint32_t sb = sm2u32(smem);
    int tid = threadIdx.x, w = tid >> 5, lane = tid & 31;
    int m0 = blockIdx.x * 128, n0 = blockIdx.y * 64;

    const __nv_bfloat16* Asrc[3] = {g_Ah, g_Am, g_Al};
    const __nv_bfloat16* Bsrc[3] = {g_Wh, g_Wm, g_Wl};

    float ps[8][4], pc[8][4];
#pragma unroll
    for (int i = 0; i < 8; i++)
#pragma unroll
        for (int j = 0; j < 4; j++) { ps[i][j] = 0.f; pc[i][j] = 0.f; }

    int aRow = w * 16 + (lane & 7) + ((lane >> 3) & 1) * 8;
    int aCol = ((lane >> 4) & 1) * 16;
    int bRow = (lane & 7) + ((lane >> 4) & 1) * 8;
    int bCol = ((lane >> 3) & 1) * 16;

    const int nch = KP / 64;
    for (int ch = 0; ch < nch; ch++) {
        const int k0 = ch * 64;
#pragma unroll
        for (int l = 0; l < 12; l++) {
            int e = tid + l * 256;
            int s = e >> 10, rem = e & 1023, m = rem >> 3, j = rem & 7;
            uint4 v = *reinterpret_cast<const uint4*>(
                Asrc[s] + (size_t)(m0 + m) * KP + k0 + j * 8);
            *reinterpret_cast<uint4*>(smem + s * ASPL + m * ROWB + j * 16) = v;
        }
#pragma unroll
        for (int l = 0; l < 6; l++) {
            int e = tid + l * 256;
            int s = e >> 9, rem = e & 511, n = rem >> 3, j = rem & 7;
            uint4 v = make_uint4(0u, 0u, 0u, 0u);
            if (n0 + n < N)
                v = *reinterpret_cast<const uint4*>(
                    Bsrc[s] + (size_t)(n0 + n) * KP + k0 + j * 8);
            *reinterpret_cast<uint4*>(smem + SMEM_B0 + s * BSPL + n * ROWB + j * 16) = v;
        }
        __syncthreads();

        float acc[8][4];
#pragma unroll
        for (int i = 0; i < 8; i++)
#pragma unroll
            for (int j = 0; j < 4; j++) acc[i][j] = 0.f;

#pragma unroll
        for (int ks = 0; ks < 4; ks++) {
            uint32_t af[3][4];
#pragma unroll
            for (int s = 0; s < 3; s++)
                LDMX4(af[s][0], af[s][1], af[s][2], af[s][3],
                      sb + s * ASPL + aRow * ROWB + ks * 32 + aCol);
#pragma unroll
            for (int q = 0; q < 4; q++) {
                uint32_t bfr[3][4];
#pragma unroll
                for (int s = 0; s < 3; s++)
                    LDMX4(bfr[s][0], bfr[s][1], bfr[s][2], bfr[s][3],
                          sb + SMEM_B0 + s * BSPL + (q * 16 + bRow) * ROWB +
                          ks * 32 + bCol);
                const int pa[6] = {0, 2, 1, 0, 1, 0};
                const int pb[6] = {2, 0, 1, 1, 0, 0};
#pragma unroll
                for (int p = 0; p < 6; p++) {
                    MMA16816(acc[2 * q],     af[pa[p]], bfr[pb[p]][0], bfr[pb[p]][1]);
                    MMA16816(acc[2 * q + 1], af[pa[p]], bfr[pb[p]][2], bfr[pb[p]][3]);
                }
            }
        }
#pragma unroll
        for (int i = 0; i < 8; i++)
#pragma unroll
            for (int j = 0; j < 4; j++) kmerge(acc[i][j], ps[i][j], pc[i][j]);
        __syncthreads();
    }

    int r = lane >> 2, cp = (lane & 3) * 2;
#pragma unroll
    for (int nb = 0; nb < 8; nb++) {
        int n = n0 + nb * 8 + cp;
        int m = m0 + w * 16 + r;
        if (n < N) {
            Cdst[(size_t)m * N + n] =
                __fadd_rn(__fsub_rn(ps[nb][0], pc[nb][0]), bias[n]);
            Cdst[(size_t)(m + 8) * N + n] =
                __fadd_rn(__fsub_rn(ps[nb][2], pc[nb][2]), bias[n]);
        }
        if (n + 1 < N) {
            Cdst[(size_t)m * N + n + 1] =
                __fadd_rn(__fsub_rn(ps[nb][1], pc[nb][1]), bias[n + 1]);
            Cdst[(size_t)(m + 8) * N + n + 1] =
                __fadd_rn(__fsub_rn(ps[nb][3], pc[nb][3]), bias[n + 1]);
        }
    }
}

// ------------------------- BN stats: fp64, row-unrolled (MLP 16) ------------
__global__ void bn_stats_kernel() {
    int blk = blockIdx.x;
    int tid = threadIdx.x;
    double ls[4] = {0.0, 0.0, 0.0, 0.0};
    double lq[4] = {0.0, 0.0, 0.0, 0.0};
    int r0 = blk * 32;
    for (int rr = 0; rr < 32; rr += 4) {
        float v[4][4];
#pragma unroll
        for (int u = 0; u < 4; u++) {
            const float* row = g_buf0 + (size_t)(r0 + rr + u) * DIN;
#pragma unroll
            for (int j = 0; j < 4; j++) {
                int c = tid + j * 256;
                v[u][j] = (c < DIN) ? row[c] : 0.f;
            }
        }
#pragma unroll
        for (int u = 0; u < 4; u++)
#pragma unroll
            for (int j = 0; j < 4; j++) {
                double d = (double)v[u][j];
                ls[j] += d;
                lq[j] += d * d;
            }
    }
#pragma unroll
    for (int j = 0; j < 4; j++) {
        int c = tid + j * 256;
        if (c < DIN) {
            g_psumd[blk * DIN + c] = ls[j];
            g_psqd [blk * DIN + c] = lq[j];
        }
    }
}

__global__ void bn_fin_kernel() {
    int c = blockIdx.x * blockDim.x + threadIdx.x;
    if (c >= DIN) return;
    double s = 0.0, q = 0.0;
    for (int i = 0; i < NSTATB; i++) {
        s += g_psumd[i * DIN + c];
        q += g_psqd [i * DIN + c];
    }
    float sumf = (float)s;
    g_mean[c] = __fdiv_rn(sumf, (float)MROWS);
    double meand = s / (double)MROWS;
    double vard = q / (double)MROWS - meand * meand;
    float var = (float)vard;
    g_rs[c] = rsqrtf(__fadd_rn(var, EPS_BN));
}

// ------- fused BN apply + sigmoid + axon1, 2 channels/thread, bf16 out ------
__global__ void axon1_bn_split_kernel(const float* __restrict__ gamma,
                                      const float* __restrict__ beta,
                                      const float* __restrict__ a1,
                                      const float* __restrict__ a2) {
    const int HD = DIN / 2;   // 392
    int idx = blockIdx.x * blockDim.x + threadIdx.x;
    if (idx >= BATCH * HD) return;
    int b = idx / HD, c2 = idx - b * HD;
    int c = c2 * 2;
    float A1x = a1[c], A1y = a1[c + 1];
    float A2x = a2[c], A2y = a2[c + 1];
    float mnx = g_mean[c], mny = g_mean[c + 1];
    float rsx = g_rs[c], rsy = g_rs[c + 1];
    float gmx = gamma[c], gmy = gamma[c + 1];
    float btx = beta[c], bty = beta[c + 1];
    float p1x = 0.f, p2x = 0.f, p1y = 0.f, p2y = 0.f;
    const float2* src = reinterpret_cast<const float2*>(
        g_buf0 + (size_t)b * T_STEPS * DIN + c);
    __nv_bfloat162* dh = reinterpret_cast<__nv_bfloat162*>(
        g_Ah + (size_t)b * T_STEPS * KP1 + c);
    __nv_bfloat162* dm = reinterpret_cast<__nv_bfloat162*>(
        g_Am + (size_t)b * T_STEPS * KP1 + c);
    __nv_bfloat162* dl = reinterpret_cast<__nv_bfloat162*>(
        g_Al + (size_t)b * T_STEPS * KP1 + c);
    for (int t = 0; t < T_STEPS; t++) {
        float2 z = *src;
        src += DIN / 2;
        float vx = __fadd_rn(__fmul_rn(__fmul_rn(gmx, __fsub_rn(z.x, mnx)), rsx), btx);
        float vy = __fadd_rn(__fmul_rn(__fmul_rn(gmy, __fsub_rn(z.y, mny)), rsy), bty);
        float xx = sigmoid_exact(vx);
        float xy = sigmoid_exact(vy);
        float px = __fadd_rn(__fadd_rn(__fmul_rn(A1x, p1x), __fmul_rn(A2x, p2x)), xx);
        float py = __fadd_rn(__fadd_rn(__fmul_rn(A1y, p1y), __fmul_rn(A2y, p2y)), xy);
        __nv_bfloat16 hx, mx, lx, hy, my, ly;
        bsplit(px, hx, mx, lx);
        bsplit(py, hy, my, ly);
        __nv_bfloat162 hv; hv.x = hx; hv.y = hy;
        __nv_bfloat162 mv; mv.x = mx; mv.y = my;
        __nv_bfloat162 lv; lv.x = lx; lv.y = ly;
        *dh = hv; *dm = mv; *dl = lv;
        dh += KP1 / 2; dm += KP1 / 2; dl += KP1 / 2;
        p2x = p1x; p1x = px;
        p2y = p1y; p1y = py;
    }
}

// ---- fused LIF + mask + axon, 2 ch/thread, writes bf16x3 (KP2 layout) ------
__global__ void lif_axon_split_kernel(int bsel, const float* __restrict__ mask,
                                      const float* __restrict__ a1,
                                      const float* __restrict__ a2) {
    const int HD = HID / 2;   // 250
    float* buf = bufsel(bsel);
    int idx = blockIdx.x * blockDim.x + threadIdx.x;
    if (idx >= BATCH * HD) return;
    int b = idx / HD, c2 = idx - b * HD;
    int c = c2 * 2;
    float A1x = a1[c], A1y = a1[c + 1];
    float A2x = a2[c], A2y = a2[c + 1];
    float vx = 0.f, spx = 0.f, vy = 0.f, spy = 0.f;
    float p1x = 0.f, p2x = 0.f, p1y = 0.f, p2y = 0.f;
    const float2* src = reinterpret_cast<const float2*>(
        buf + (size_t)b * T_STEPS * HID + c);
    __nv_bfloat162* dh = reinterpret_cast<__nv_bfloat162*>(
        g_Ah + (size_t)b * T_STEPS * KP2 + c);
    __nv_bfloat162* dm = reinterpret_cast<__nv_bfloat162*>(
        g_Am + (size_t)b * T_STEPS * KP2 + c);
    __nv_bfloat162* dl = reinterpret_cast<__nv_bfloat162*>(
        g_Al + (size_t)b * T_STEPS * KP2 + c);
    const float* mrow0 = mask + (size_t)(b * HID + c) * T_STEPS;
    const float* mrow1 = mrow0 + T_STEPS;
    for (int t = 0; t < T_STEPS; t++) {
        float2 z = *src;
        src += HID / 2;
        vx = __fadd_rn(__fmul_rn(__fmul_rn(DECAY_M, vx), __fsub_rn(1.0f, spx)), z.x);
        vy = __fadd_rn(__fmul_rn(__fmul_rn(DECAY_M, vy), __fsub_rn(1.0f, spy)), z.y);
        spx = (vx > 1.0f) ? 1.0f : 0.0f;
        spy = (vy > 1.0f) ? 1.0f : 0.0f;
        float xx = __fmul_rn(spx, mrow0[t]);
        float xy = __fmul_rn(spy, mrow1[t]);
        float px = __fadd_rn(__fadd_rn(__fmul_rn(A1x, p1x), __fmul_rn(A2x, p2x)), xx);
        float py = __fadd_rn(__fadd_rn(__fmul_rn(A1y, p1y), __fmul_rn(A2y, p2y)), xy);
        __nv_bfloat16 hx, mx, lx, hy, my, ly;
        bsplit(px, hx, mx, lx);
        bsplit(py, hy, my, ly);
        __nv_bfloat162 hv; hv.x = hx; hv.y = hy;
        __nv_bfloat162 mv; mv.x = mx; mv.y = my;
        __nv_bfloat162 lv; lv.x = lx; lv.y = ly;
        *dh = hv; *dm = mv; *dl = lv;
        dh += KP2 / 2; dm += KP2 / 2; dl += KP2 / 2;
        p2x = p1x; p1x = px;
        p2y = p1y; p1y = py;
    }
}

// ---- fused LIF + mask + axon, 2 ch/thread, fp32 out (feeds gemm3) ----------
__global__ void lif_axon_kernel(int bsel, const float* __restrict__ mask,
                                const float* __restrict__ a1,
                                const float* __restrict__ a2) {
    const int HD = HID / 2;
    float* buf = bufsel(bsel);
    int idx = blockIdx.x * blockDim.x + threadIdx.x;
    if (idx >= BATCH * HD) return;
    int b = idx / HD, c2 = idx - b * HD;
    int c = c2 * 2;
    float A1x = a1[c], A1y = a1[c + 1];
    float A2x = a2[c], A2y = a2[c + 1];
    float vx = 0.f, spx = 0.f, vy = 0.f, spy = 0.f;
    float p1x = 0.f, p2x = 0.f, p1y = 0.f, p2y = 0.f;
    float2* src = reinterpret_cast<float2*>(buf + (size_t)b * T_STEPS * HID + c);
    const float* mrow0 = mask + (size_t)(b * HID + c) * T_STEPS;
    const float* mrow1 = mrow0 + T_STEPS;
    for (int t = 0; t < T_STEPS; t++) {
        float2 z = *src;
        vx = __fadd_rn(__fmul_rn(__fmul_rn(DECAY_M, vx), __fsub_rn(1.0f, spx)), z.x);
        vy = __fadd_rn(__fmul_rn(__fmul_rn(DECAY_M, vy), __fsub_rn(1.0f, spy)), z.y);
        spx = (vx > 1.0f) ? 1.0f : 0.0f;
        spy = (vy > 1.0f) ? 1.0f : 0.0f;
        float px = __fadd_rn(__fadd_rn(__fmul_rn(A1x, p1x), __fmul_rn(A2x, p2x)),
                             __fmul_rn(spx, mrow0[t]));
        float py = __fadd_rn(__fadd_rn(__fmul_rn(A1y, p1y), __fmul_rn(A2y, p2y)),
                             __fmul_rn(spy, mrow1[t]));
        float2 o; o.x = px; o.y = py;
        *src = o;
        src += HID / 2;
        p2x = p1x; p1x = px;
        p2y = p1y; p1y = py;
    }
}

// ------------------------- GEMM3 (N=10): compensated ------------------------
__global__ void __launch_bounds__(256) gemm3_kernel(
    const float* __restrict__ W3, const float* __restrict__ b3) {
    __shared__ float sW[NOUT][HID];
    int tid = threadIdx.x;
    for (int i = tid; i < NOUT * HID; i += 256) sW[i / HID][i % HID] = W3[i];
    __syncthreads();
    int idx = blockIdx.x * 256 + tid;
    int r = idx / NOUT, o = idx - r * NOUT;
    const float* a = g_buf2 + r * HID;
    float s = 0.f, c = 0.f;
    for (int k = 0; k < HID; k++) kacc2(a[k], sW[o][k], s, c);
    float acc = __fsub_rn(s, c);
    g_buf3[r * NOUT + o] = __fadd_rn(acc, b3[o]);
}

// ------------------------- final LIF + output transpose [B,10,T] ------------
__global__ void lif3_out_kernel(float* __restrict__ out) {
    int idx = blockIdx.x * blockDim.x + threadIdx.x;
    if (idx >= BATCH * NOUT) return;
    int b = idx / NOUT, o = idx - b * NOUT;
    float v = 0.f, s = 0.f;
    for (int t = 0; t < T_STEPS; t++) {
        float z = g_buf3[(b * T_STEPS + t) * NOUT + o];
        v = __fadd_rn(__fmul_rn(__fmul_rn(DECAY_M, v), __fsub_rn(1.0f, s)), z);
        s = (v > 1.0f) ? 1.0f : 0.0f;
        out[(b * NOUT + o) * T_STEPS + t] = s;
    }
}

// ------------------------- launch -------------------------------------------
extern "C" void kernel_launch(void* const* d_in, const int* in_sizes, int n_in,
                              void* d_out, int out_size) {
    const float* inputs = (const float*)d_in[0];
    const float* W_mlp  = (const float*)d_in[1];
    const float* b_mlp  = (const float*)d_in[2];
    const float* gamma  = (const float*)d_in[3];
    const float* beta   = (const float*)d_in[4];
    const float* a1_1   = (const float*)d_in[5];
    const float* a2_1   = (const float*)d_in[6];
    const float* W1     = (const float*)d_in[7];
    const float* b1     = (const float*)d_in[8];
    const float* a1_2   = (const float*)d_in[9];
    const float* a2_2   = (const float*)d_in[10];
    const float* W2     = (const float*)d_in[11];
    const float* b2     = (const float*)d_in[12];
    const float* a1_3   = (const float*)d_in[13];
    const float* a2_3   = (const float*)d_in[14];
    const float* W3     = (const float*)d_in[15];
    const float* b3     = (const float*)d_in[16];
    const float* mask1  = (const float*)d_in[17];
    const float* mask2  = (const float*)d_in[18];
    float* out = (float*)d_out;

    static int smem_set = 0;
    if (!smem_set) {
        cudaFuncSetAttribute(mma_gemm_kernel,
                             cudaFuncAttributeMaxDynamicSharedMemorySize, SMEM_TOT);
        smem_set = 1;
    }

    // ---- GEMM MLP
    split_a_mlp_t_kernel<<<dim3(BATCH, 7, 26), dim3(32, 8)>>>(inputs);
    split_w_kernel<<<(DIN * KP1 + 255) / 256, 256>>>(W_mlp, DIN, DIN, KP1);
    mma_gemm_kernel<<<dim3(MROWS / 128, (DIN + 63) / 64), 256, SMEM_TOT>>>(
        b_mlp, 0, DIN, KP1);

    bn_stats_kernel<<<NSTATB, 256>>>();
    bn_fin_kernel<<<(DIN + 255) / 256, 256>>>();
    axon1_bn_split_kernel<<<(BATCH * (DIN / 2) + 255) / 256, 256>>>(
        gamma, beta, a1_1, a2_1);

    // ---- GEMM1
    split_w_kernel<<<(HID * KP1 + 255) / 256, 256>>>(W1, HID, DIN, KP1);
    mma_gemm_kernel<<<dim3(MROWS / 128, (HID + 63) / 64), 256, SMEM_TOT>>>(
        b1, 1, HID, KP1);
    lif_axon_split_kernel<<<(BATCH * (HID / 2) + 255) / 256, 256>>>(
        1, mask1, a1_2, a2_2);
    zero_pad2_kernel<<<(MROWS * (KP2 - HID) + 255) / 256, 256>>>();

    // ---- GEMM2
    split_w_kernel<<<(HID * KP2 + 255) / 256, 256>>>(W2, HID, HID, KP2);
    mma_gemm_kernel<<<dim3(MROWS / 128, (HID + 63) / 64), 256, SMEM_TOT>>>(
        b2, 2, HID, KP2);
    lif_axon_kernel<<<(BATCH * (HID / 2) + 255) / 256, 256>>>(
        2, mask2, a1_3, a2_3);

    // ---- GEMM3 + output
    gemm3_kernel<<<MROWS * NOUT / 256, 256>>>(W3, b3);
    lif3_out_kernel<<<(BATCH * NOUT + 255) / 256, 256>>>(out);
}